// round 1
// baseline (speedup 1.0000x reference)
#include <cuda_runtime.h>
#include <cuda_bf16.h>
#include <cstdint>

// Problem constants
#define N_NODES 100000
#define N_EDGES 1600000
#define D_IN    128
#define D_HID   256
#define D_OUT   128
// Pad M to a multiple of 128 so GEMM A-loads need no bounds checks.
#define NPAD    100096   // 782 * 128

// Scratch (static device globals — no cudaMalloc allowed)
__device__ float g_AX[(size_t)NPAD * D_IN];   // (1+eps)*x + segment_sum(val*x[src])
__device__ float g_H[(size_t)NPAD * D_HID];   // relu(AX@W1 + b1)

// ---------------------------------------------------------------------------
// Kernel 1: AX = (1+eps)*x  (valid rows), 0 (pad rows)
// ---------------------------------------------------------------------------
__global__ void init_ax_kernel(const float* __restrict__ x,
                               const float* __restrict__ eps) {
    const float scale = 1.0f + eps[0];
    const size_t total = (size_t)NPAD * D_IN / 4;
    const size_t valid = (size_t)N_NODES * D_IN / 4;
    float4* __restrict__ AX4 = reinterpret_cast<float4*>(g_AX);
    const float4* __restrict__ x4 = reinterpret_cast<const float4*>(x);
    size_t stride = (size_t)gridDim.x * blockDim.x;
    for (size_t i = (size_t)blockIdx.x * blockDim.x + threadIdx.x; i < total; i += stride) {
        if (i < valid) {
            float4 v = x4[i];
            v.x *= scale; v.y *= scale; v.z *= scale; v.w *= scale;
            AX4[i] = v;
        } else {
            AX4[i] = make_float4(0.f, 0.f, 0.f, 0.f);
        }
    }
}

// ---------------------------------------------------------------------------
// Kernel 2: edge scatter.  One warp per edge; each lane handles one float4 of
// the 128-float row; vector RED (red.global.add.v4.f32) into AX[dst].
// ---------------------------------------------------------------------------
__global__ void scatter_edges_kernel(const float* __restrict__ x,
                                     const float* __restrict__ vals,
                                     const int*   __restrict__ src,
                                     const int*   __restrict__ dst) {
    const int lane = threadIdx.x & 31;
    const int warp = (blockIdx.x * blockDim.x + threadIdx.x) >> 5;
    const int nwarps = (gridDim.x * blockDim.x) >> 5;
    for (int e = warp; e < N_EDGES; e += nwarps) {
        const int   s = __ldg(&src[e]);
        const int   d = __ldg(&dst[e]);
        const float v = __ldg(&vals[e]);
        const float4 xi = reinterpret_cast<const float4*>(x + (size_t)s * D_IN)[lane];
        float* out = g_AX + (size_t)d * D_IN + lane * 4;
        asm volatile("red.global.add.v4.f32 [%0], {%1, %2, %3, %4};"
                     :: "l"(out), "f"(v * xi.x), "f"(v * xi.y),
                        "f"(v * xi.z), "f"(v * xi.w)
                     : "memory");
    }
}

// ---------------------------------------------------------------------------
// Kernel 3/4: tiled fp32 GEMM  C = op(A@B + bias), A:[M,K] B:[K,N] row-major.
// BM=BN=128, BK=8, 256 threads, 8x8 register micro-tile. Fused bias (+relu).
// Assumes M % BM == 0 and N % BN == 0 and K % BK == 0 (true: M=NPAD, N∈{128,256},
// K∈{128,256}). Store guarded by storeM for the final output.
// ---------------------------------------------------------------------------
template<bool RELU, bool GUARD>
__global__ __launch_bounds__(256, 2)
void sgemm_bias_kernel(const float* __restrict__ A,
                       const float* __restrict__ B,
                       const float* __restrict__ bias,
                       float* __restrict__ C,
                       int M, int N, int K, int storeM) {
    constexpr int BM = 128, BN = 128, BK = 8, TM = 8, TN = 8;
    __shared__ float As[BK][BM];   // transposed A tile
    __shared__ float Bs[BK][BN];

    const int tid = threadIdx.x;
    const int threadRow = tid / 16;        // 0..15
    const int threadCol = tid % 16;        // 0..15
    const int blockRow = blockIdx.y;
    const int blockCol = blockIdx.x;

    // A tile load mapping: 128 rows x 8 cols = 1024 floats = 256 x float4
    const int innerRowA = tid / 2;         // 0..127
    const int innerColA = (tid % 2) * 4;   // 0 or 4
    // B tile load mapping: 8 rows x 128 cols
    const int innerRowB = tid / 32;        // 0..7
    const int innerColB = (tid % 32) * 4;  // 0..124

    const float* Aptr = A + (size_t)(blockRow * BM + innerRowA) * K + innerColA;
    const float* Bptr = B + (size_t)innerRowB * N + blockCol * BN + innerColB;

    float acc[TM][TN];
    #pragma unroll
    for (int i = 0; i < TM; i++)
        #pragma unroll
        for (int j = 0; j < TN; j++) acc[i][j] = 0.f;

    for (int kb = 0; kb < K; kb += BK) {
        float4 a4 = *reinterpret_cast<const float4*>(Aptr + kb);
        As[innerColA + 0][innerRowA] = a4.x;
        As[innerColA + 1][innerRowA] = a4.y;
        As[innerColA + 2][innerRowA] = a4.z;
        As[innerColA + 3][innerRowA] = a4.w;
        float4 b4 = *reinterpret_cast<const float4*>(Bptr + (size_t)kb * N);
        *reinterpret_cast<float4*>(&Bs[innerRowB][innerColB]) = b4;
        __syncthreads();

        #pragma unroll
        for (int k = 0; k < BK; k++) {
            float4 m0 = *reinterpret_cast<const float4*>(&As[k][threadRow * TM]);
            float4 m1 = *reinterpret_cast<const float4*>(&As[k][threadRow * TM + 4]);
            float4 n0 = *reinterpret_cast<const float4*>(&Bs[k][threadCol * TN]);
            float4 n1 = *reinterpret_cast<const float4*>(&Bs[k][threadCol * TN + 4]);
            float rm[TM] = {m0.x, m0.y, m0.z, m0.w, m1.x, m1.y, m1.z, m1.w};
            float rn[TN] = {n0.x, n0.y, n0.z, n0.w, n1.x, n1.y, n1.z, n1.w};
            #pragma unroll
            for (int i = 0; i < TM; i++)
                #pragma unroll
                for (int j = 0; j < TN; j++)
                    acc[i][j] = fmaf(rm[i], rn[j], acc[i][j]);
        }
        __syncthreads();
    }

    // Epilogue: bias, optional relu, vectorized store (guarded for output rows)
    const int nBase = blockCol * BN + threadCol * TN;
    float bv[TN];
    #pragma unroll
    for (int j = 0; j < TN; j++) bv[j] = bias[nBase + j];

    #pragma unroll
    for (int i = 0; i < TM; i++) {
        const int row = blockRow * BM + threadRow * TM + i;
        if (GUARD && row >= storeM) continue;
        float r[TN];
        #pragma unroll
        for (int j = 0; j < TN; j++) {
            float vv = acc[i][j] + bv[j];
            if (RELU) vv = fmaxf(vv, 0.f);
            r[j] = vv;
        }
        float* cp = C + (size_t)row * N + nBase;
        *reinterpret_cast<float4*>(cp)     = make_float4(r[0], r[1], r[2], r[3]);
        *reinterpret_cast<float4*>(cp + 4) = make_float4(r[4], r[5], r[6], r[7]);
    }
}

// ---------------------------------------------------------------------------
// kernel_launch: init -> scatter -> gemm1(relu) -> gemm2
// Input order (metadata): x, edge_vals, W1, b1, W2, b2, eps, edge_src, edge_dst
// ---------------------------------------------------------------------------
extern "C" void kernel_launch(void* const* d_in, const int* in_sizes, int n_in,
                              void* d_out, int out_size) {
    const float* x    = (const float*)d_in[0];
    const float* ev   = (const float*)d_in[1];
    const float* W1   = (const float*)d_in[2];
    const float* b1   = (const float*)d_in[3];
    const float* W2   = (const float*)d_in[4];
    const float* b2   = (const float*)d_in[5];
    const float* eps  = (const float*)d_in[6];
    const int*   esrc = (const int*)d_in[7];
    const int*   edst = (const int*)d_in[8];
    float* out = (float*)d_out;

    float* AX; cudaGetSymbolAddress((void**)&AX, g_AX);
    float* H;  cudaGetSymbolAddress((void**)&H,  g_H);

    // 1) AX = (1+eps)*x (pad rows zeroed)
    init_ax_kernel<<<1184, 256>>>(x, eps);

    // 2) AX[dst] += val * x[src]
    scatter_edges_kernel<<<4736, 256>>>(x, ev, esrc, edst);

    // 3) H = relu(AX @ W1 + b1)   [NPAD x 256]
    {
        dim3 grid(D_HID / 128, NPAD / 128);
        sgemm_bias_kernel<true, false><<<grid, 256>>>(AX, W1, b1, H,
                                                      NPAD, D_HID, D_IN, NPAD);
    }

    // 4) out = H @ W2 + b2        [N_NODES x 128]
    {
        dim3 grid(D_OUT / 128, NPAD / 128);
        sgemm_bias_kernel<false, true><<<grid, 256>>>(H, W2, b2, out,
                                                      NPAD, D_OUT, D_HID, N_NODES);
    }
}

// round 3
// speedup vs baseline: 1.7719x; 1.7719x over previous
#include <cuda_runtime.h>
#include <cuda_bf16.h>
#include <cstdint>

// Problem constants
#define N_NODES 100000
#define N_EDGES 1600000
#define D_IN    128
#define D_HID   256
#define D_OUT   128
#define NPAD    100096   // 782 * 128, pad M so GEMM A-loads need no bounds checks

// Scratch (static device globals — no cudaMalloc allowed)
__device__ float g_AX[(size_t)NPAD * D_IN];   // (1+eps)*x + segment_sum(val*x[src])
__device__ float g_H[(size_t)NPAD * D_HID];   // relu(AX@W1 + b1)

// ---------------------------------------------------------------------------
// Kernel 1: AX = (1+eps)*x  (valid rows), 0 (pad rows)
// ---------------------------------------------------------------------------
__global__ void init_ax_kernel(const float* __restrict__ x,
                               const float* __restrict__ eps) {
    const float scale = 1.0f + eps[0];
    const size_t total = (size_t)NPAD * D_IN / 4;
    const size_t valid = (size_t)N_NODES * D_IN / 4;
    float4* __restrict__ AX4 = reinterpret_cast<float4*>(g_AX);
    const float4* __restrict__ x4 = reinterpret_cast<const float4*>(x);
    size_t stride = (size_t)gridDim.x * blockDim.x;
    for (size_t i = (size_t)blockIdx.x * blockDim.x + threadIdx.x; i < total; i += stride) {
        if (i < valid) {
            float4 v = x4[i];
            v.x *= scale; v.y *= scale; v.z *= scale; v.w *= scale;
            AX4[i] = v;
        } else {
            AX4[i] = make_float4(0.f, 0.f, 0.f, 0.f);
        }
    }
}

// ---------------------------------------------------------------------------
// Kernel 2: edge scatter. One warp per edge, vector RED into AX[dst].
// ---------------------------------------------------------------------------
__global__ void scatter_edges_kernel(const float* __restrict__ x,
                                     const float* __restrict__ vals,
                                     const int*   __restrict__ src,
                                     const int*   __restrict__ dst) {
    const int lane = threadIdx.x & 31;
    const int warp = (blockIdx.x * blockDim.x + threadIdx.x) >> 5;
    const int nwarps = (gridDim.x * blockDim.x) >> 5;
    for (int e = warp; e < N_EDGES; e += nwarps) {
        const int   s = __ldg(&src[e]);
        const int   d = __ldg(&dst[e]);
        const float v = __ldg(&vals[e]);
        const float4 xi = reinterpret_cast<const float4*>(x + (size_t)s * D_IN)[lane];
        float* out = g_AX + (size_t)d * D_IN + lane * 4;
        asm volatile("red.global.add.v4.f32 [%0], {%1, %2, %3, %4};"
                     :: "l"(out), "f"(v * xi.x), "f"(v * xi.y),
                        "f"(v * xi.z), "f"(v * xi.w)
                     : "memory");
    }
}

// ---------------------------------------------------------------------------
// TF32 tensor-core GEMM: C = op(A@B + bias)
// A:[NPAD,K] row-major fp32, B:[K,N] row-major fp32.
// CTA tile 128x128, BK=16, double-buffered smem, 8 warps (2 x 4),
// warp tile 64x32, mma.sync.m16n8k8.tf32 with ldmatrix for A fragments.
// Inputs rounded to tf32 (cvt.rna) at the global->smem stage; fp32 accumulate.
// ---------------------------------------------------------------------------
__device__ __forceinline__ uint32_t f2tf32(float x) {
    uint32_t r;
    asm("cvt.rna.tf32.f32 %0, %1;" : "=r"(r) : "f"(x));
    return r;
}

template<int K, int N, bool RELU, bool GUARD>
__global__ __launch_bounds__(256)
void mma_gemm_kernel(const float* __restrict__ A, const float* __restrict__ B,
                     const float* __restrict__ bias, float* __restrict__ C,
                     int storeM) {
    constexpr int BM = 128, BN = 128, BK = 16;
    constexpr int KT = K / BK;
    constexpr int SA = BK + 4;   // 20 floats: rows 80B (16B-aligned), ldmatrix conflict-free
    constexpr int SB = BN + 4;   // 132 floats: rows 528B (16B-aligned)

    __shared__ float As[2][BM][SA];
    __shared__ float Bs[2][BK][SB];

    const int tid  = threadIdx.x;
    const int lane = tid & 31;
    const int wid  = tid >> 5;
    const int warp_m = wid & 1;    // 0..1 -> 64 rows each
    const int warp_n = wid >> 1;   // 0..3 -> 32 cols each
    const int bm0 = blockIdx.y * BM;
    const int bn0 = blockIdx.x * BN;

    // Global->smem mappings (each thread: 2 float4 for A, 2 float4 for B)
    const int arow = tid >> 2;          // 0..63 (second at +64)
    const int akq  = (tid & 3) * 4;
    const int brow = tid >> 5;          // 0..7 (second at +8)
    const int bnq  = (tid & 31) * 4;

    const float* Ag = A + (size_t)(bm0 + arow) * K + akq;
    const float* Bg = B + (size_t)brow * N + bn0 + bnq;

    float acc[4][4][4];
    #pragma unroll
    for (int i = 0; i < 4; i++)
        #pragma unroll
        for (int j = 0; j < 4; j++)
            #pragma unroll
            for (int c = 0; c < 4; c++) acc[i][j][c] = 0.f;

    float4 ra0, ra1, rb0, rb1;

    // Prologue: load tile 0 and commit to buffer 0
    ra0 = *reinterpret_cast<const float4*>(Ag);
    ra1 = *reinterpret_cast<const float4*>(Ag + (size_t)64 * K);
    rb0 = *reinterpret_cast<const float4*>(Bg);
    rb1 = *reinterpret_cast<const float4*>(Bg + (size_t)8 * N);
    {
        float4 c0 = make_float4(__uint_as_float(f2tf32(ra0.x)), __uint_as_float(f2tf32(ra0.y)),
                                __uint_as_float(f2tf32(ra0.z)), __uint_as_float(f2tf32(ra0.w)));
        float4 c1 = make_float4(__uint_as_float(f2tf32(ra1.x)), __uint_as_float(f2tf32(ra1.y)),
                                __uint_as_float(f2tf32(ra1.z)), __uint_as_float(f2tf32(ra1.w)));
        float4 c2 = make_float4(__uint_as_float(f2tf32(rb0.x)), __uint_as_float(f2tf32(rb0.y)),
                                __uint_as_float(f2tf32(rb0.z)), __uint_as_float(f2tf32(rb0.w)));
        float4 c3 = make_float4(__uint_as_float(f2tf32(rb1.x)), __uint_as_float(f2tf32(rb1.y)),
                                __uint_as_float(f2tf32(rb1.z)), __uint_as_float(f2tf32(rb1.w)));
        *reinterpret_cast<float4*>(&As[0][arow][akq])      = c0;
        *reinterpret_cast<float4*>(&As[0][arow + 64][akq]) = c1;
        *reinterpret_cast<float4*>(&Bs[0][brow][bnq])      = c2;
        *reinterpret_cast<float4*>(&Bs[0][brow + 8][bnq])  = c3;
    }
    __syncthreads();

    // ldmatrix per-lane addressing (fixed for the whole kernel)
    const int lsub = lane >> 3;                  // 0..3: which 8x4 sub-matrix
    const int lrow = (lane & 7) + (lsub & 1) * 8;
    const int lkof = (lsub >> 1) * 4;

    for (int kt = 0; kt < KT; kt++) {
        const int cur = kt & 1;
        const bool more = (kt + 1 < KT);
        if (more) {
            const float* Ag2 = Ag + (kt + 1) * BK;
            const float* Bg2 = Bg + (size_t)(kt + 1) * BK * N;
            ra0 = *reinterpret_cast<const float4*>(Ag2);
            ra1 = *reinterpret_cast<const float4*>(Ag2 + (size_t)64 * K);
            rb0 = *reinterpret_cast<const float4*>(Bg2);
            rb1 = *reinterpret_cast<const float4*>(Bg2 + (size_t)8 * N);
        }

        #pragma unroll
        for (int k8 = 0; k8 < 2; k8++) {
            const int k0 = k8 * 8;
            // A fragments: 4 m-tiles via ldmatrix.x4
            uint32_t af[4][4];
            #pragma unroll
            for (int mt = 0; mt < 4; mt++) {
                const float* p = &As[cur][warp_m * 64 + mt * 16 + lrow][k0 + lkof];
                uint32_t ad = (uint32_t)__cvta_generic_to_shared(p);
                asm volatile("ldmatrix.sync.aligned.m8n8.x4.shared.b16 {%0,%1,%2,%3}, [%4];"
                             : "=r"(af[mt][0]), "=r"(af[mt][1]),
                               "=r"(af[mt][2]), "=r"(af[mt][3])
                             : "r"(ad));
            }
            // B fragments: 4 n-tiles, scalar LDS (col-major frag layout)
            uint32_t bf[4][2];
            const int bk0 = k0 + (lane & 3);
            const int bnb = warp_n * 32 + (lane >> 2);
            #pragma unroll
            for (int nt = 0; nt < 4; nt++) {
                bf[nt][0] = *reinterpret_cast<const uint32_t*>(&Bs[cur][bk0][bnb + nt * 8]);
                bf[nt][1] = *reinterpret_cast<const uint32_t*>(&Bs[cur][bk0 + 4][bnb + nt * 8]);
            }
            #pragma unroll
            for (int mt = 0; mt < 4; mt++)
                #pragma unroll
                for (int nt = 0; nt < 4; nt++) {
                    asm volatile(
                        "mma.sync.aligned.m16n8k8.row.col.f32.tf32.tf32.f32 "
                        "{%0,%1,%2,%3}, {%4,%5,%6,%7}, {%8,%9}, {%0,%1,%2,%3};"
                        : "+f"(acc[mt][nt][0]), "+f"(acc[mt][nt][1]),
                          "+f"(acc[mt][nt][2]), "+f"(acc[mt][nt][3])
                        : "r"(af[mt][0]), "r"(af[mt][1]), "r"(af[mt][2]), "r"(af[mt][3]),
                          "r"(bf[nt][0]), "r"(bf[nt][1]));
                }
        }

        if (more) {
            const int nxt = cur ^ 1;
            float4 c0 = make_float4(__uint_as_float(f2tf32(ra0.x)), __uint_as_float(f2tf32(ra0.y)),
                                    __uint_as_float(f2tf32(ra0.z)), __uint_as_float(f2tf32(ra0.w)));
            float4 c1 = make_float4(__uint_as_float(f2tf32(ra1.x)), __uint_as_float(f2tf32(ra1.y)),
                                    __uint_as_float(f2tf32(ra1.z)), __uint_as_float(f2tf32(ra1.w)));
            float4 c2 = make_float4(__uint_as_float(f2tf32(rb0.x)), __uint_as_float(f2tf32(rb0.y)),
                                    __uint_as_float(f2tf32(rb0.z)), __uint_as_float(f2tf32(rb0.w)));
            float4 c3 = make_float4(__uint_as_float(f2tf32(rb1.x)), __uint_as_float(f2tf32(rb1.y)),
                                    __uint_as_float(f2tf32(rb1.z)), __uint_as_float(f2tf32(rb1.w)));
            *reinterpret_cast<float4*>(&As[nxt][arow][akq])      = c0;
            *reinterpret_cast<float4*>(&As[nxt][arow + 64][akq]) = c1;
            *reinterpret_cast<float4*>(&Bs[nxt][brow][bnq])      = c2;
            *reinterpret_cast<float4*>(&Bs[nxt][brow + 8][bnq])  = c3;
        }
        __syncthreads();
    }

    // Epilogue: bias (+relu), float2 stores, guarded by storeM
    const int g  = lane >> 2;
    const int t4 = lane & 3;
    #pragma unroll
    for (int nt = 0; nt < 4; nt++) {
        const int col = bn0 + warp_n * 32 + nt * 8 + 2 * t4;
        const float2 bv = *reinterpret_cast<const float2*>(&bias[col]);
        #pragma unroll
        for (int mt = 0; mt < 4; mt++) {
            const int row0 = bm0 + warp_m * 64 + mt * 16 + g;
            float v0 = acc[mt][nt][0] + bv.x;
            float v1 = acc[mt][nt][1] + bv.y;
            float v2 = acc[mt][nt][2] + bv.x;
            float v3 = acc[mt][nt][3] + bv.y;
            if (RELU) {
                v0 = fmaxf(v0, 0.f); v1 = fmaxf(v1, 0.f);
                v2 = fmaxf(v2, 0.f); v3 = fmaxf(v3, 0.f);
            }
            if (!GUARD || row0 < storeM)
                *reinterpret_cast<float2*>(C + (size_t)row0 * N + col) = make_float2(v0, v1);
            if (!GUARD || row0 + 8 < storeM)
                *reinterpret_cast<float2*>(C + (size_t)(row0 + 8) * N + col) = make_float2(v2, v3);
        }
    }
}

// ---------------------------------------------------------------------------
// kernel_launch: init -> scatter -> gemm1(relu) -> gemm2
// Input order: x, edge_vals, W1, b1, W2, b2, eps, edge_src, edge_dst
// ---------------------------------------------------------------------------
extern "C" void kernel_launch(void* const* d_in, const int* in_sizes, int n_in,
                              void* d_out, int out_size) {
    const float* x    = (const float*)d_in[0];
    const float* ev   = (const float*)d_in[1];
    const float* W1   = (const float*)d_in[2];
    const float* b1   = (const float*)d_in[3];
    const float* W2   = (const float*)d_in[4];
    const float* b2   = (const float*)d_in[5];
    const float* eps  = (const float*)d_in[6];
    const int*   esrc = (const int*)d_in[7];
    const int*   edst = (const int*)d_in[8];
    float* out = (float*)d_out;

    float* AX; cudaGetSymbolAddress((void**)&AX, g_AX);
    float* H;  cudaGetSymbolAddress((void**)&H,  g_H);

    // 1) AX = (1+eps)*x (pad rows zeroed)
    init_ax_kernel<<<1184, 256>>>(x, eps);

    // 2) AX[dst] += val * x[src]
    scatter_edges_kernel<<<4736, 256>>>(x, ev, esrc, edst);

    // 3) H = relu(AX @ W1 + b1)   [NPAD x 256]
    {
        dim3 grid(D_HID / 128, NPAD / 128);
        mma_gemm_kernel<D_IN, D_HID, true, false><<<grid, 256>>>(AX, W1, b1, H, NPAD);
    }

    // 4) out = H @ W2 + b2        [N_NODES x 128]
    {
        dim3 grid(D_OUT / 128, NPAD / 128);
        mma_gemm_kernel<D_HID, D_OUT, false, true><<<grid, 256>>>(H, W2, b2, out, N_NODES);
    }
}